// round 2
// baseline (speedup 1.0000x reference)
#include <cuda_runtime.h>

#define NB   2
#define CIN  16
#define CM   24
#define HIN  384
#define WIN  1280
#define HO   96
#define WL   320
#define WR   1280
#define DMAX 64

// scratch (device globals: no allocation allowed)
__device__ float g_fl[(size_t)NB*CM*HO*WL];
__device__ float g_fr[(size_t)NB*CM*HO*WR];

typedef unsigned long long ull;

__device__ __forceinline__ ull pack2(float lo, float hi) {
    ull r; asm("mov.b64 %0,{%1,%2};" : "=l"(r) : "f"(lo), "f"(hi)); return r;
}
__device__ __forceinline__ void unpack2(ull v, float& lo, float& hi) {
    asm("mov.b64 {%0,%1},%2;" : "=f"(lo), "=f"(hi) : "l"(v));
}
__device__ __forceinline__ ull fma2(ull a, ull b, ull c) {
    ull d; asm("fma.rn.f32x2 %0,%1,%2,%3;" : "=l"(d) : "l"(a), "l"(b), "l"(c)); return d;
}
__device__ __forceinline__ ull lrelu2(ull v) {
    float lo, hi; unpack2(v, lo, hi);
    lo = lo > 0.f ? lo : 0.2f * lo;
    hi = hi > 0.f ? hi : 0.2f * hi;
    return pack2(lo, hi);
}

#define SM_EM (CM*CIN*16)   // 6144 packed weights
#define SM_RC (CM*CM)       // 576
#define SMW_ULL (SM_EM + SM_RC + 2*CM)

__device__ __forceinline__ void load_weights_smem(ull* sm, const float* wem, const float* bem,
                                                  const float* wrc, const float* brc, int tid, int nthr) {
    ull* sw_em = sm;
    ull* sw_rc = sm + SM_EM;
    ull* sb_em = sw_rc + SM_RC;
    ull* sb_rc = sb_em + CM;
    for (int i = tid; i < SM_EM; i += nthr) { float w = wem[i]; sw_em[i] = pack2(w, w); }
    for (int i = tid; i < SM_RC; i += nthr) { float w = wrc[i]; sw_rc[i] = pack2(w, w); }
    if (tid < CM) { float v = bem[tid]; sb_em[tid] = pack2(v, v);
                    v = brc[tid];       sb_rc[tid] = pack2(v, v); }
}

// ---------------- left branch: 4x4 conv stride(4,4) VALID + leaky + 1x1 + leaky ----------------
__global__ void __launch_bounds__(160) conv_left_kernel(
    const float* __restrict__ in, const float* __restrict__ wem, const float* __restrict__ bem,
    const float* __restrict__ wrc, const float* __restrict__ brc)
{
    extern __shared__ ull sm[];
    ull* sw_em = sm;
    ull* sw_rc = sm + SM_EM;
    ull* sb_em = sw_rc + SM_RC;
    ull* sb_rc = sb_em + CM;
    const int tid = threadIdx.x;
    load_weights_smem(sm, wem, bem, wrc, brc, tid, 160);
    __syncthreads();

    const int h = blockIdx.x, b = blockIdx.y;
    const int w0 = 2 * tid;                 // output pixel pair (w0, w0+1)

    ull acc[CM];
    #pragma unroll
    for (int c = 0; c < CM; c++) acc[c] = sb_em[c];

    const float* inb = in + (size_t)b * CIN * HIN * WIN;
    #pragma unroll 1
    for (int ci = 0; ci < CIN; ci++) {
        #pragma unroll
        for (int kh = 0; kh < 4; kh++) {
            const float* row = inb + ((size_t)(ci * HIN + 4 * h + kh)) * WIN + 4 * w0;
            const float4 va = *(const float4*)row;        // cols for pixel w0
            const float4 vb = *(const float4*)(row + 4);  // cols for pixel w0+1
            const float cA[4] = {va.x, va.y, va.z, va.w};
            const float cB[4] = {vb.x, vb.y, vb.z, vb.w};
            #pragma unroll
            for (int kw = 0; kw < 4; kw++) {
                const ull x2 = pack2(cA[kw], cB[kw]);
                const ull* wp = sw_em + (ci * 4 + kh) * 4 + kw;
                #pragma unroll
                for (int c = 0; c < CM; c++)
                    acc[c] = fma2(x2, wp[c * 256], acc[c]);
            }
        }
    }
    #pragma unroll
    for (int c = 0; c < CM; c++) acc[c] = lrelu2(acc[c]);

    #pragma unroll 1
    for (int co = 0; co < CM; co++) {
        ull s = sb_rc[co];
        #pragma unroll
        for (int c = 0; c < CM; c++) s = fma2(acc[c], sw_rc[co * CM + c], s);
        s = lrelu2(s);
        float lo, hi; unpack2(s, lo, hi);
        *(float2*)(g_fl + (((size_t)b * CM + co) * HO + h) * WL + w0) = make_float2(lo, hi);
    }
}

// ---------------- right branch: 4x4 conv stride(4,1), SAME-ish pad (pl=1,pr=2) ----------------
__global__ void __launch_bounds__(160) conv_right_kernel(
    const float* __restrict__ in, const float* __restrict__ wem, const float* __restrict__ bem,
    const float* __restrict__ wrc, const float* __restrict__ brc)
{
    extern __shared__ ull sm[];
    ull* sw_em = sm;
    ull* sw_rc = sm + SM_EM;
    ull* sb_em = sw_rc + SM_RC;
    ull* sb_rc = sb_em + CM;
    const int tid = threadIdx.x;
    load_weights_smem(sm, wem, bem, wrc, brc, tid, 160);
    __syncthreads();

    const int h = blockIdx.y, b = blockIdx.z;
    const int w0 = blockIdx.x * 320 + 2 * tid;   // pixel pair

    ull acc[CM];
    #pragma unroll
    for (int c = 0; c < CM; c++) acc[c] = sb_em[c];

    const float* inb = in + (size_t)b * CIN * HIN * WIN;
    #pragma unroll 1
    for (int ci = 0; ci < CIN; ci++) {
        #pragma unroll
        for (int kh = 0; kh < 4; kh++) {
            const float* row = inb + ((size_t)(ci * HIN + 4 * h + kh)) * WIN;
            float c0[5];
            #pragma unroll
            for (int j = 0; j < 5; j++) {
                int col = w0 - 1 + j;   // pixel w0 reads cols w0-1..w0+2, pixel w0+1 reads w0..w0+3
                c0[j] = (col >= 0 && col < WIN) ? row[col] : 0.f;
            }
            #pragma unroll
            for (int kw = 0; kw < 4; kw++) {
                const ull x2 = pack2(c0[kw], c0[kw + 1]);
                const ull* wp = sw_em + (ci * 4 + kh) * 4 + kw;
                #pragma unroll
                for (int c = 0; c < CM; c++)
                    acc[c] = fma2(x2, wp[c * 256], acc[c]);
            }
        }
    }
    #pragma unroll
    for (int c = 0; c < CM; c++) acc[c] = lrelu2(acc[c]);

    #pragma unroll 1
    for (int co = 0; co < CM; co++) {
        ull s = sb_rc[co];
        #pragma unroll
        for (int c = 0; c < CM; c++) s = fma2(acc[c], sw_rc[co * CM + c], s);
        s = lrelu2(s);
        float lo, hi; unpack2(s, lo, hi);
        *(float2*)(g_fr + (((size_t)b * CM + co) * HO + h) * WR + w0) = make_float2(lo, hi);
    }
}

// ---------------- cost volume + min/argmin + 25->13 1x1 conv + assemble ----------------
#define FR_STRIDE 1284   // 1280 data + offset 2 + pad to multiple of 4 (keeps rows 16B aligned)

__global__ void __launch_bounds__(320) cost_kernel(
    const float* __restrict__ wtf, const float* __restrict__ btf, float* __restrict__ out)
{
    extern __shared__ float s[];
    float* s_fr  = s;                         // [CM][FR_STRIDE], data at word offset +2
    float* s_fl  = s + CM * FR_STRIDE;        // [CM][WL]
    float* s_wtf = s_fl + CM * WL;            // 13*25
    float* s_btf = s_wtf + 13 * 25;           // 13

    const int x = threadIdx.x;
    const int h = blockIdx.x, b = blockIdx.y;

    #pragma unroll 1
    for (int c = 0; c < CM; c++) {
        const float4 v = *(const float4*)(g_fr + (((size_t)b * CM + c) * HO + h) * WR + 4 * x);
        float* d = s_fr + c * FR_STRIDE + 2 + 4 * x;
        d[0] = v.x; d[1] = v.y; d[2] = v.z; d[3] = v.w;
        s_fl[c * WL + x] = g_fl[(((size_t)b * CM + c) * HO + h) * WL + x];
    }
    for (int i = x; i < 13 * 25; i += 320) s_wtf[i] = wtf[i];
    if (x < 13) s_btf[x] = btf[x];
    __syncthreads();

    float acc[DMAX];
    #pragma unroll
    for (int d = 0; d < DMAX; d++) acc[d] = 0.f;

    if (x >= 16) {
        // no clipping possible: idx = 4x+1-d >= 4*16+1-63 = 2 >= 0
        // word layout: s_fr[c][2+i] = fr[i]; float4 at index (x-dq) covers words 4x-4dq..+3,
        // i.e. fr[4x-4dq-2 .. 4x-4dq+1]  ->  v.w = d=4dq+0, v.z = d=4dq+1, v.y = +2, v.x = +3
        #pragma unroll 1
        for (int c = 0; c < CM; c++) {
            const float flc = s_fl[c * WL + x];
            const float4* rp = (const float4*)(s_fr + c * FR_STRIDE);
            #pragma unroll
            for (int dq = 0; dq < 16; dq++) {
                const float4 v = rp[x - dq];
                acc[4 * dq + 0] += fabsf(flc - v.w);
                acc[4 * dq + 1] += fabsf(flc - v.z);
                acc[4 * dq + 2] += fabsf(flc - v.y);
                acc[4 * dq + 3] += fabsf(flc - v.x);
            }
        }
    } else {
        #pragma unroll 1
        for (int c = 0; c < CM; c++) {
            const float flc = s_fl[c * WL + x];
            const float* rp = s_fr + c * FR_STRIDE + 2;
            #pragma unroll 1
            for (int d = 0; d < DMAX; d++) {
                int idx = 4 * x + 1 - d;
                if (idx < 0) idx = 0;
                acc[d] += fabsf(flc - rp[idx]);
            }
        }
    }

    // cost_volume out: [B, D, H, WL] right after out tensor [B,16,H,WL]
    float* cv = out + (size_t)NB * 16 * HO * WL;
    #pragma unroll 1
    for (int d = 0; d < DMAX; d++)
        cv[(((size_t)b * DMAX + d) * HO + h) * WL + x] = acc[d];

    // min + argmin (first occurrence, matches jnp.argmin)
    float best = acc[0]; int bi = 0;
    #pragma unroll
    for (int d = 1; d < DMAX; d++)
        if (acc[d] < best) { best = acc[d]; bi = d; }

    // 25 -> 13 1x1 conv: input ch0 = best cost, ch1..24 = fl channels
    float o13[13];
    #pragma unroll
    for (int o = 0; o < 13; o++) o13[o] = s_btf[o] + s_wtf[o * 25] * best;
    #pragma unroll 1
    for (int c = 0; c < CM; c++) {
        const float v = s_fl[c * WL + x];
        #pragma unroll
        for (int o = 0; o < 13; o++) o13[o] += s_wtf[o * 25 + 1 + c] * v;
    }

    out[(((size_t)b * 16 + 0) * HO + h) * WL + x] = (float)bi;
    out[(((size_t)b * 16 + 1) * HO + h) * WL + x] = 0.f;
    out[(((size_t)b * 16 + 2) * HO + h) * WL + x] = 0.f;
    #pragma unroll
    for (int o = 0; o < 13; o++) {
        float v = o13[o];
        v = v > 0.f ? v : 0.2f * v;
        out[(((size_t)b * 16 + 3 + o) * HO + h) * WL + x] = v;
    }
}

extern "C" void kernel_launch(void* const* d_in, const int* in_sizes, int n_in,
                              void* d_out, int out_size)
{
    const float* fl  = (const float*)d_in[0];
    const float* fr  = (const float*)d_in[1];
    // d_in[2] = max_disp (int32 scalar, fixed 64)
    const float* wem = (const float*)d_in[3];
    const float* bem = (const float*)d_in[4];
    const float* wrc = (const float*)d_in[5];
    const float* brc = (const float*)d_in[6];
    const float* wtf = (const float*)d_in[7];
    const float* btf = (const float*)d_in[8];
    float* out = (float*)d_out;

    const size_t smw = (size_t)SMW_ULL * sizeof(ull);                       // 54,144 B
    const size_t sm2 = (size_t)(CM * FR_STRIDE + CM * WL + 13 * 25 + 13) * sizeof(float); // 155,336 B

    cudaFuncSetAttribute(conv_left_kernel,  cudaFuncAttributeMaxDynamicSharedMemorySize, (int)smw);
    cudaFuncSetAttribute(conv_right_kernel, cudaFuncAttributeMaxDynamicSharedMemorySize, (int)smw);
    cudaFuncSetAttribute(cost_kernel,       cudaFuncAttributeMaxDynamicSharedMemorySize, (int)sm2);

    conv_left_kernel <<<dim3(HO, NB),            160, smw>>>(fl, wem, bem, wrc, brc);
    conv_right_kernel<<<dim3(WR / 320, HO, NB),  160, smw>>>(fr, wem, bem, wrc, brc);
    cost_kernel      <<<dim3(HO, NB),            320, sm2>>>(wtf, btf, out);
}

// round 4
// speedup vs baseline: 1.2855x; 1.2855x over previous
#include <cuda_runtime.h>

#define NB   2
#define CIN  16
#define CM   24
#define HIN  384
#define WIN  1280
#define HO   96
#define WL   320
#define WR   1280
#define DMAX 64

// scratch (device globals: no allocation allowed)
__device__ float g_fl[(size_t)NB*CM*HO*WL];
__device__ float g_fr[(size_t)NB*CM*HO*WR];

typedef unsigned long long ull;

__device__ __forceinline__ ull pack2(float lo, float hi) {
    ull r; asm("mov.b64 %0,{%1,%2};" : "=l"(r) : "f"(lo), "f"(hi)); return r;
}
__device__ __forceinline__ void unpack2(ull v, float& lo, float& hi) {
    asm("mov.b64 {%0,%1},%2;" : "=f"(lo), "=f"(hi) : "l"(v));
}
__device__ __forceinline__ ull fma2(ull a, ull b, ull c) {
    ull d; asm("fma.rn.f32x2 %0,%1,%2,%3;" : "=l"(d) : "l"(a), "l"(b), "l"(c)); return d;
}
__device__ __forceinline__ ull lrelu2(ull v) {
    float lo, hi; unpack2(v, lo, hi);
    lo = lo > 0.f ? lo : 0.2f * lo;
    hi = hi > 0.f ? hi : 0.2f * hi;
    return pack2(lo, hi);
}

// smem weight layout:
//   em: s[((ci*4+kh)*CM + c)*4 + kw]   (kw of one channel contiguous -> LDS.128 pairs)
//   rc: s2[co*CM + c]
#define SM_EM (CIN*16*CM)      // 6144 ull
#define SM_RC (CM*CM)          // 576 ull
#define SMW_ULL (SM_EM + SM_RC + 2*CM)

#define NLEFT_BLK 120          // 2*96*80 / 128
#define NRIGHT_BLK 480         // 2*96*320 / 128

__device__ __forceinline__ void load_weights_smem(ull* sm, const float* wem, const float* bem,
                                                  const float* wrc, const float* brc, int tid, int nthr) {
    ull* sw_em = sm;
    ull* sw_rc = sm + SM_EM;
    ull* sb_em = sw_rc + SM_RC;
    ull* sb_rc = sb_em + CM;
    for (int i = tid; i < SM_EM; i += nthr) {
        int kw = i & 3;
        int rest = i >> 2;
        int c  = rest % CM;
        int r2 = rest / CM;          // ci*4 + kh
        int kh = r2 & 3, ci = r2 >> 2;
        float w = wem[((c * CIN + ci) * 4 + kh) * 4 + kw];
        sw_em[i] = pack2(w, w);
    }
    for (int i = tid; i < SM_RC; i += nthr) { float w = wrc[i]; sw_rc[i] = pack2(w, w); }
    if (tid < CM) { float v = bem[tid]; sb_em[tid] = pack2(v, v);
                    v = brc[tid];       sb_rc[tid] = pack2(v, v); }
}

template<bool RIGHT>
__device__ __forceinline__ void conv_body(const float* __restrict__ in, const ull* sm, int g)
{
    const ull* sw_em = sm;
    const ull* sw_rc = sm + SM_EM;
    const ull* sb_em = sw_rc + SM_RC;
    const ull* sb_rc = sb_em + CM;

    const int TPR = RIGHT ? 320 : 80;   // pixel-quads per row
    const int t  = g % TPR;
    const int hh = (g / TPR) % HO;
    const int b  = g / (TPR * HO);

    ull acc0[CM], acc1[CM];
    #pragma unroll
    for (int c = 0; c < CM; c++) { acc0[c] = sb_em[c]; acc1[c] = sb_em[c]; }

    const float* inb = in + (size_t)b * CIN * HIN * WIN;

    #pragma unroll 1
    for (int ci = 0; ci < CIN; ci++) {
        #pragma unroll
        for (int kh = 0; kh < 4; kh++) {
            const float* row = inb + (size_t)(ci * HIN + 4 * hh + kh) * WIN;
            ull xA[4], xB[4];
            if (RIGHT) {
                // pixels 4t..4t+3, input cols 4t-1..4t+5 (pad: pl=1, pr=2)
                const float4 vb = *(const float4*)(row + 4 * t);
                float4 va = make_float4(0.f, 0.f, 0.f, 0.f);
                float4 vc = make_float4(0.f, 0.f, 0.f, 0.f);
                if (t > 0)   va = *(const float4*)(row + 4 * t - 4);
                if (t < 319) vc = *(const float4*)(row + 4 * t + 4);
                const float r0 = va.w, r1 = vb.x, r2 = vb.y, r3 = vb.z,
                            r4 = vb.w, r5 = vc.x, r6 = vc.y;
                xA[0] = pack2(r0, r1); xA[1] = pack2(r1, r2);
                xA[2] = pack2(r2, r3); xA[3] = pack2(r3, r4);
                xB[0] = xA[2];         xB[1] = xA[3];
                xB[2] = pack2(r4, r5); xB[3] = pack2(r5, r6);
            } else {
                // pixels 4t..4t+3, input cols 16t .. 16t+15 (stride 4, no overlap)
                const float4 v0 = *(const float4*)(row + 16 * t);
                const float4 v1 = *(const float4*)(row + 16 * t + 4);
                const float4 v2 = *(const float4*)(row + 16 * t + 8);
                const float4 v3 = *(const float4*)(row + 16 * t + 12);
                xA[0] = pack2(v0.x, v1.x); xA[1] = pack2(v0.y, v1.y);
                xA[2] = pack2(v0.z, v1.z); xA[3] = pack2(v0.w, v1.w);
                xB[0] = pack2(v2.x, v3.x); xB[1] = pack2(v2.y, v3.y);
                xB[2] = pack2(v2.z, v3.z); xB[3] = pack2(v2.w, v3.w);
            }
            const ull* wp = sw_em + (ci * 4 + kh) * (CM * 4);
            #pragma unroll
            for (int c = 0; c < CM; c++) {
                const ulonglong2 w01 = *(const ulonglong2*)(wp + c * 4);
                const ulonglong2 w23 = *(const ulonglong2*)(wp + c * 4 + 2);
                acc0[c] = fma2(xA[0], w01.x, acc0[c]);
                acc0[c] = fma2(xA[1], w01.y, acc0[c]);
                acc0[c] = fma2(xA[2], w23.x, acc0[c]);
                acc0[c] = fma2(xA[3], w23.y, acc0[c]);
                acc1[c] = fma2(xB[0], w01.x, acc1[c]);
                acc1[c] = fma2(xB[1], w01.y, acc1[c]);
                acc1[c] = fma2(xB[2], w23.x, acc1[c]);
                acc1[c] = fma2(xB[3], w23.y, acc1[c]);
            }
        }
    }

    #pragma unroll
    for (int c = 0; c < CM; c++) { acc0[c] = lrelu2(acc0[c]); acc1[c] = lrelu2(acc1[c]); }

    float* gout = RIGHT ? g_fr : g_fl;
    const int W = RIGHT ? WR : WL;

    #pragma unroll 2
    for (int co = 0; co < CM; co++) {
        ull s0 = sb_rc[co], s1 = sb_rc[co];
        #pragma unroll
        for (int cp = 0; cp < CM / 2; cp++) {
            const ulonglong2 w = *(const ulonglong2*)(sw_rc + co * CM + 2 * cp);
            s0 = fma2(acc0[2 * cp], w.x, s0);
            s0 = fma2(acc0[2 * cp + 1], w.y, s0);
            s1 = fma2(acc1[2 * cp], w.x, s1);
            s1 = fma2(acc1[2 * cp + 1], w.y, s1);
        }
        s0 = lrelu2(s0); s1 = lrelu2(s1);
        float a, bq, c2, d2;
        unpack2(s0, a, bq); unpack2(s1, c2, d2);
        *(float4*)(gout + (((size_t)b * CM + co) * HO + hh) * W + 4 * t) =
            make_float4(a, bq, c2, d2);
    }
}

__global__ void __launch_bounds__(128) conv_fused_kernel(
    const float* __restrict__ inL, const float* __restrict__ inR,
    const float* __restrict__ wem, const float* __restrict__ bem,
    const float* __restrict__ wrc, const float* __restrict__ brc)
{
    extern __shared__ ull sm[];
    load_weights_smem(sm, wem, bem, wrc, brc, threadIdx.x, 128);
    __syncthreads();
    const int gb = blockIdx.x;
    if (gb < NLEFT_BLK) conv_body<false>(inL, sm, gb * 128 + threadIdx.x);
    else                conv_body<true >(inR, sm, (gb - NLEFT_BLK) * 128 + threadIdx.x);
}

// ---------------- cost volume + min/argmin + 25->13 1x1 conv + assemble ----------------
#define FR_STRIDE 1284   // 1280 data + word offset 2 + pad (rows stay 16B aligned)

__global__ void __launch_bounds__(320) cost_kernel(
    const float* __restrict__ wtf, const float* __restrict__ btf, float* __restrict__ out)
{
    extern __shared__ float s[];
    float* s_fr  = s;                         // [CM][FR_STRIDE], data at word offset +2
    float* s_fl  = s + CM * FR_STRIDE;        // [CM][WL]
    float* s_wtf = s_fl + CM * WL;            // 13*25
    float* s_btf = s_wtf + 13 * 25;           // 13

    const int x = threadIdx.x;
    const int h = blockIdx.x, b = blockIdx.y;

    #pragma unroll 1
    for (int c = 0; c < CM; c++) {
        const float4 v = *(const float4*)(g_fr + (((size_t)b * CM + c) * HO + h) * WR + 4 * x);
        float* d = s_fr + c * FR_STRIDE + 2 + 4 * x;
        d[0] = v.x; d[1] = v.y; d[2] = v.z; d[3] = v.w;
        s_fl[c * WL + x] = g_fl[(((size_t)b * CM + c) * HO + h) * WL + x];
    }
    for (int i = x; i < 13 * 25; i += 320) s_wtf[i] = wtf[i];
    if (x < 13) s_btf[x] = btf[x];
    __syncthreads();

    float acc[DMAX];
    #pragma unroll
    for (int d = 0; d < DMAX; d++) acc[d] = 0.f;

    if (x >= 16) {
        // no clipping possible: idx = 4x+1-d >= 2
        #pragma unroll 1
        for (int c = 0; c < CM; c++) {
            const float flc = s_fl[c * WL + x];
            const float4* rp = (const float4*)(s_fr + c * FR_STRIDE);
            #pragma unroll
            for (int dq = 0; dq < 16; dq++) {
                const float4 v = rp[x - dq];
                acc[4 * dq + 0] += fabsf(flc - v.w);
                acc[4 * dq + 1] += fabsf(flc - v.z);
                acc[4 * dq + 2] += fabsf(flc - v.y);
                acc[4 * dq + 3] += fabsf(flc - v.x);
            }
        }
    } else {
        #pragma unroll 1
        for (int c = 0; c < CM; c++) {
            const float flc = s_fl[c * WL + x];
            const float* rp = s_fr + c * FR_STRIDE + 2;
            #pragma unroll 1
            for (int d = 0; d < DMAX; d++) {
                int idx = 4 * x + 1 - d;
                if (idx < 0) idx = 0;
                acc[d] += fabsf(flc - rp[idx]);
            }
        }
    }

    // cost_volume out: [B, D, H, WL] after out tensor [B,16,H,WL]
    float* cv = out + (size_t)NB * 16 * HO * WL;
    #pragma unroll 1
    for (int d = 0; d < DMAX; d++)
        cv[(((size_t)b * DMAX + d) * HO + h) * WL + x] = acc[d];

    // min + argmin (first occurrence, matches jnp.argmin)
    float best = acc[0]; int bi = 0;
    #pragma unroll
    for (int d = 1; d < DMAX; d++)
        if (acc[d] < best) { best = acc[d]; bi = d; }

    // 25 -> 13 1x1 conv: ch0 = best cost, ch1..24 = fl channels
    float o13[13];
    #pragma unroll
    for (int o = 0; o < 13; o++) o13[o] = s_btf[o] + s_wtf[o * 25] * best;
    #pragma unroll 1
    for (int c = 0; c < CM; c++) {
        const float v = s_fl[c * WL + x];
        #pragma unroll
        for (int o = 0; o < 13; o++) o13[o] += s_wtf[o * 25 + 1 + c] * v;
    }

    out[(((size_t)b * 16 + 0) * HO + h) * WL + x] = (float)bi;
    out[(((size_t)b * 16 + 1) * HO + h) * WL + x] = 0.f;
    out[(((size_t)b * 16 + 2) * HO + h) * WL + x] = 0.f;
    #pragma unroll
    for (int o = 0; o < 13; o++) {
        float v = o13[o];
        v = v > 0.f ? v : 0.2f * v;
        out[(((size_t)b * 16 + 3 + o) * HO + h) * WL + x] = v;
    }
}

extern "C" void kernel_launch(void* const* d_in, const int* in_sizes, int n_in,
                              void* d_out, int out_size)
{
    const float* fl  = (const float*)d_in[0];
    const float* fr  = (const float*)d_in[1];
    // d_in[2] = max_disp (int32 scalar, fixed 64)
    const float* wem = (const float*)d_in[3];
    const float* bem = (const float*)d_in[4];
    const float* wrc = (const float*)d_in[5];
    const float* brc = (const float*)d_in[6];
    const float* wtf = (const float*)d_in[7];
    const float* btf = (const float*)d_in[8];
    float* out = (float*)d_out;

    const size_t smw = (size_t)SMW_ULL * sizeof(ull);
    const size_t sm2 = (size_t)(CM * FR_STRIDE + CM * WL + 13 * 25 + 13) * sizeof(float);

    cudaFuncSetAttribute(conv_fused_kernel, cudaFuncAttributeMaxDynamicSharedMemorySize, (int)smw);
    cudaFuncSetAttribute(cost_kernel,       cudaFuncAttributeMaxDynamicSharedMemorySize, (int)sm2);

    conv_fused_kernel<<<NLEFT_BLK + NRIGHT_BLK, 128, smw>>>(fl, fr, wem, bem, wrc, brc);
    cost_kernel      <<<dim3(HO, NB), 320, sm2>>>(wtf, btf, out);
}

// round 7
// speedup vs baseline: 2.2314x; 1.7358x over previous
#include <cuda_runtime.h>

#define NB   2
#define CIN  16
#define CM   24
#define HIN  384
#define WIN  1280
#define HO   96
#define WL   320
#define WR   1280
#define DMAX 64

// scratch (device globals: no allocation allowed)
__device__ float g_fl[(size_t)NB*CM*HO*WL];
__device__ float g_fr[(size_t)NB*CM*HO*WR];

typedef unsigned long long ull;

__device__ __forceinline__ ull pack2(float lo, float hi) {
    ull r; asm("mov.b64 %0,{%1,%2};" : "=l"(r) : "f"(lo), "f"(hi)); return r;
}
__device__ __forceinline__ void unpack2(ull v, float& lo, float& hi) {
    asm("mov.b64 {%0,%1},%2;" : "=f"(lo), "=f"(hi) : "l"(v));
}
__device__ __forceinline__ ull fma2(ull a, ull b, ull c) {
    ull d; asm("fma.rn.f32x2 %0,%1,%2,%3;" : "=l"(d) : "l"(a), "l"(b), "l"(c)); return d;
}
__device__ __forceinline__ ull lrelu2(ull v) {
    float lo, hi; unpack2(v, lo, hi);
    lo = lo > 0.f ? lo : 0.2f * lo;
    hi = hi > 0.f ? hi : 0.2f * hi;
    return pack2(lo, hi);
}

// smem weight layout:
//   em: s[((ci*4+kh)*CM + c)*4 + kw]   (kw of one channel contiguous -> LDS.128 pairs)
//   rc: s2[co*CM + c]
#define SM_EM (CIN*16*CM)      // 6144 ull
#define SM_RC (CM*CM)          // 576 ull
#define SMW_ULL (SM_EM + SM_RC + 2*CM)

#define NLEFT_BLK 120          // 2*96*80 / 128
#define NRIGHT_BLK 480         // 2*96*320 / 128

__device__ __forceinline__ void load_weights_smem(ull* sm, const float* wem, const float* bem,
                                                  const float* wrc, const float* brc, int tid, int nthr) {
    ull* sw_em = sm;
    ull* sw_rc = sm + SM_EM;
    ull* sb_em = sw_rc + SM_RC;
    ull* sb_rc = sb_em + CM;
    for (int i = tid; i < SM_EM; i += nthr) {
        int kw = i & 3;
        int rest = i >> 2;
        int c  = rest % CM;
        int r2 = rest / CM;          // ci*4 + kh
        int kh = r2 & 3, ci = r2 >> 2;
        float w = wem[((c * CIN + ci) * 4 + kh) * 4 + kw];
        sw_em[i] = pack2(w, w);
    }
    for (int i = tid; i < SM_RC; i += nthr) { float w = wrc[i]; sw_rc[i] = pack2(w, w); }
    if (tid < CM) { float v = bem[tid]; sb_em[tid] = pack2(v, v);
                    v = brc[tid];       sb_rc[tid] = pack2(v, v); }
}

template<bool RIGHT>
__device__ __forceinline__ void conv_body(const float* __restrict__ in, const ull* sm, int g)
{
    const ull* sw_em = sm;
    const ull* sw_rc = sm + SM_EM;
    const ull* sb_em = sw_rc + SM_RC;
    const ull* sb_rc = sb_em + CM;

    const int TPR = RIGHT ? 320 : 80;   // pixel-quads per row
    const int t  = g % TPR;
    const int hh = (g / TPR) % HO;
    const int b  = g / (TPR * HO);

    ull acc0[CM], acc1[CM];
    #pragma unroll
    for (int c = 0; c < CM; c++) { acc0[c] = sb_em[c]; acc1[c] = sb_em[c]; }

    const float* inb = in + (size_t)b * CIN * HIN * WIN;

    #pragma unroll 1
    for (int ci = 0; ci < CIN; ci++) {
        #pragma unroll
        for (int kh = 0; kh < 4; kh++) {
            const float* row = inb + (size_t)(ci * HIN + 4 * hh + kh) * WIN;
            ull xA[4], xB[4];
            if (RIGHT) {
                // pixels 4t..4t+3, input cols 4t-1..4t+5 (pad: pl=1, pr=2)
                const float4 vb = *(const float4*)(row + 4 * t);
                float4 va = make_float4(0.f, 0.f, 0.f, 0.f);
                float4 vc = make_float4(0.f, 0.f, 0.f, 0.f);
                if (t > 0)   va = *(const float4*)(row + 4 * t - 4);
                if (t < 319) vc = *(const float4*)(row + 4 * t + 4);
                const float r0 = va.w, r1 = vb.x, r2 = vb.y, r3 = vb.z,
                            r4 = vb.w, r5 = vc.x, r6 = vc.y;
                xA[0] = pack2(r0, r1); xA[1] = pack2(r1, r2);
                xA[2] = pack2(r2, r3); xA[3] = pack2(r3, r4);
                xB[0] = xA[2];         xB[1] = xA[3];
                xB[2] = pack2(r4, r5); xB[3] = pack2(r5, r6);
            } else {
                // pixels 4t..4t+3, input cols 16t .. 16t+15 (stride 4, no overlap)
                const float4 v0 = *(const float4*)(row + 16 * t);
                const float4 v1 = *(const float4*)(row + 16 * t + 4);
                const float4 v2 = *(const float4*)(row + 16 * t + 8);
                const float4 v3 = *(const float4*)(row + 16 * t + 12);
                xA[0] = pack2(v0.x, v1.x); xA[1] = pack2(v0.y, v1.y);
                xA[2] = pack2(v0.z, v1.z); xA[3] = pack2(v0.w, v1.w);
                xB[0] = pack2(v2.x, v3.x); xB[1] = pack2(v2.y, v3.y);
                xB[2] = pack2(v2.z, v3.z); xB[3] = pack2(v2.w, v3.w);
            }
            const ull* wp = sw_em + (ci * 4 + kh) * (CM * 4);
            #pragma unroll
            for (int c = 0; c < CM; c++) {
                const ulonglong2 w01 = *(const ulonglong2*)(wp + c * 4);
                const ulonglong2 w23 = *(const ulonglong2*)(wp + c * 4 + 2);
                acc0[c] = fma2(xA[0], w01.x, acc0[c]);
                acc0[c] = fma2(xA[1], w01.y, acc0[c]);
                acc0[c] = fma2(xA[2], w23.x, acc0[c]);
                acc0[c] = fma2(xA[3], w23.y, acc0[c]);
                acc1[c] = fma2(xB[0], w01.x, acc1[c]);
                acc1[c] = fma2(xB[1], w01.y, acc1[c]);
                acc1[c] = fma2(xB[2], w23.x, acc1[c]);
                acc1[c] = fma2(xB[3], w23.y, acc1[c]);
            }
        }
    }

    #pragma unroll
    for (int c = 0; c < CM; c++) { acc0[c] = lrelu2(acc0[c]); acc1[c] = lrelu2(acc1[c]); }

    float* gout = RIGHT ? g_fr : g_fl;
    const int W = RIGHT ? WR : WL;

    #pragma unroll 2
    for (int co = 0; co < CM; co++) {
        ull s0 = sb_rc[co], s1 = sb_rc[co];
        #pragma unroll
        for (int cp = 0; cp < CM / 2; cp++) {
            const ulonglong2 w = *(const ulonglong2*)(sw_rc + co * CM + 2 * cp);
            s0 = fma2(acc0[2 * cp], w.x, s0);
            s0 = fma2(acc0[2 * cp + 1], w.y, s0);
            s1 = fma2(acc1[2 * cp], w.x, s1);
            s1 = fma2(acc1[2 * cp + 1], w.y, s1);
        }
        s0 = lrelu2(s0); s1 = lrelu2(s1);
        float a, bq, c2, d2;
        unpack2(s0, a, bq); unpack2(s1, c2, d2);
        *(float4*)(gout + (((size_t)b * CM + co) * HO + hh) * W + 4 * t) =
            make_float4(a, bq, c2, d2);
    }
}

__global__ void __launch_bounds__(128) conv_fused_kernel(
    const float* __restrict__ inL, const float* __restrict__ inR,
    const float* __restrict__ wem, const float* __restrict__ bem,
    const float* __restrict__ wrc, const float* __restrict__ brc)
{
    extern __shared__ ull sm[];
    load_weights_smem(sm, wem, bem, wrc, brc, threadIdx.x, 128);
    __syncthreads();
    const int gb = blockIdx.x;
    if (gb < NLEFT_BLK) conv_body<false>(inL, sm, gb * 128 + threadIdx.x);
    else                conv_body<true >(inR, sm, (gb - NLEFT_BLK) * 128 + threadIdx.x);
}

// ---------------- cost volume + min/argmin + 25->13 1x1 conv + assemble ----------------
// Tiled: block = (b, h, x-tile of 64). 256 threads = 4 disparity groups x 64 x.
// smem fr window: s_fr[c][j] = fr[c][4*x0 - 66 + j], j in [0,320); float4 at smem word
// index 4k covers fr[4*x0-66+4k .. +3], so float4 idx (xl+16-dq) covers
// fr[4x-4dq-2 .. 4x-4dq+1]  ->  .w = d=4dq, .z = d=4dq+1, .y = +2, .x = +3
#define XT   64
#define FRS  324    // 320 words + pad (multiple of 4)
#define WB_PAD 340  // 13*25 + 13 = 338, padded to even word count (float2 alignment for s_red)

__global__ void __launch_bounds__(256) cost_kernel(
    const float* __restrict__ wtf, const float* __restrict__ btf, float* __restrict__ out)
{
    extern __shared__ float s[];
    float*  s_fr  = s;                             // [CM][FRS]
    float*  s_fl  = s + CM * FRS;                  // [CM][XT]
    float*  s_wtf = s_fl + CM * XT;                // 13*25
    float*  s_btf = s_wtf + 13 * 25;               // 13
    float2* s_red = (float2*)(s_fl + CM * XT + WB_PAD);  // [256], 8B-aligned (even word offset)

    const int tid = threadIdx.x;
    const int xl  = tid & 63;                 // local x
    const int dg  = tid >> 6;                 // disparity group: d in [16*dg, 16*dg+15]
    const int x0  = blockIdx.x * XT;
    const int h   = blockIdx.y, b = blockIdx.z;
    const int x   = x0 + xl;

    // ---- stage smem ----
    {
        const int G0 = 4 * x0 - 66;           // even -> float2 aligned
        #pragma unroll 1
        for (int i = tid; i < CM * 160; i += 256) {
            const int c = i / 160, p = i % 160;
            const int g = G0 + 2 * p;
            float2 v = make_float2(0.f, 0.f);
            if (g >= 0 && g < WR)
                v = *(const float2*)(g_fr + (((size_t)b * CM + c) * HO + h) * WR + g);
            s_fr[c * FRS + 2 * p]     = v.x;
            s_fr[c * FRS + 2 * p + 1] = v.y;
        }
        #pragma unroll 1
        for (int i = tid; i < CM * (XT / 4); i += 256) {
            const int c = i / (XT / 4), q = i % (XT / 4);
            *(float4*)(s_fl + c * XT + 4 * q) =
                *(const float4*)(g_fl + (((size_t)b * CM + c) * HO + h) * WL + x0 + 4 * q);
        }
        for (int i = tid; i < 13 * 25; i += 256) s_wtf[i] = wtf[i];
        if (tid < 13) s_btf[tid] = btf[tid];
    }
    __syncthreads();

    // ---- accumulate 16 disparities per thread ----
    float acc[16];
    #pragma unroll
    for (int i = 0; i < 16; i++) acc[i] = 0.f;

    if (x >= 16) {
        #pragma unroll 1
        for (int c = 0; c < CM; c++) {
            const float flc = s_fl[c * XT + xl];
            const float4* rp = (const float4*)(s_fr + c * FRS);
            #pragma unroll
            for (int q = 0; q < 4; q++) {
                const int dq = 4 * dg + q;
                const float4 v = rp[xl + 16 - dq];
                acc[4 * q + 0] += fabsf(flc - v.w);
                acc[4 * q + 1] += fabsf(flc - v.z);
                acc[4 * q + 2] += fabsf(flc - v.y);
                acc[4 * q + 3] += fabsf(flc - v.x);
            }
        }
    } else {   // only tile 0, x<16: clipped indices
        #pragma unroll 1
        for (int c = 0; c < CM; c++) {
            const float flc = s_fl[c * XT + xl];
            const float* rp = s_fr + c * FRS + 66;   // rp[i] = fr[i] (x0 == 0)
            #pragma unroll
            for (int i = 0; i < 16; i++) {
                int d = 16 * dg + i;
                int idx = 4 * x + 1 - d;
                if (idx < 0) idx = 0;
                acc[i] += fabsf(flc - rp[idx]);
            }
        }
    }

    // ---- write cost volume slice ----
    float* cv = out + (size_t)NB * 16 * HO * WL;
    #pragma unroll
    for (int i = 0; i < 16; i++) {
        const int d = 16 * dg + i;
        cv[(((size_t)b * DMAX + d) * HO + h) * WL + x] = acc[i];
    }

    // ---- per-thread min/argmin (ascending d, strict < = first occurrence) ----
    float best = acc[0]; int bi = 16 * dg;
    #pragma unroll
    for (int i = 1; i < 16; i++)
        if (acc[i] < best) { best = acc[i]; bi = 16 * dg + i; }
    s_red[tid] = make_float2(best, (float)bi);
    __syncthreads();

    // ---- final reduce + 25->13 conv + assemble (64 threads) ----
    if (tid < XT) {
        float2 r = s_red[tid];
        #pragma unroll
        for (int g2 = 1; g2 < 4; g2++) {
            const float2 o = s_red[g2 * 64 + tid];
            if (o.x < r.x) r = o;
        }

        float o13[13];
        #pragma unroll
        for (int o = 0; o < 13; o++) o13[o] = s_btf[o] + s_wtf[o * 25] * r.x;
        #pragma unroll 1
        for (int c = 0; c < CM; c++) {
            const float v = s_fl[c * XT + tid];
            #pragma unroll
            for (int o = 0; o < 13; o++) o13[o] += s_wtf[o * 25 + 1 + c] * v;
        }

        out[(((size_t)b * 16 + 0) * HO + h) * WL + x0 + tid] = r.y;
        out[(((size_t)b * 16 + 1) * HO + h) * WL + x0 + tid] = 0.f;
        out[(((size_t)b * 16 + 2) * HO + h) * WL + x0 + tid] = 0.f;
        #pragma unroll
        for (int o = 0; o < 13; o++) {
            float v = o13[o];
            v = v > 0.f ? v : 0.2f * v;
            out[(((size_t)b * 16 + 3 + o) * HO + h) * WL + x0 + tid] = v;
        }
    }
}

extern "C" void kernel_launch(void* const* d_in, const int* in_sizes, int n_in,
                              void* d_out, int out_size)
{
    const float* fl  = (const float*)d_in[0];
    const float* fr  = (const float*)d_in[1];
    // d_in[2] = max_disp (int32 scalar, fixed 64)
    const float* wem = (const float*)d_in[3];
    const float* bem = (const float*)d_in[4];
    const float* wrc = (const float*)d_in[5];
    const float* brc = (const float*)d_in[6];
    const float* wtf = (const float*)d_in[7];
    const float* btf = (const float*)d_in[8];
    float* out = (float*)d_out;

    const size_t smw = (size_t)SMW_ULL * sizeof(ull);
    const size_t sm2 = (size_t)(CM * FRS + CM * XT + WB_PAD) * sizeof(float)
                     + 256 * sizeof(float2);

    cudaFuncSetAttribute(conv_fused_kernel, cudaFuncAttributeMaxDynamicSharedMemorySize, (int)smw);
    cudaFuncSetAttribute(cost_kernel,       cudaFuncAttributeMaxDynamicSharedMemorySize, (int)sm2);

    conv_fused_kernel<<<NLEFT_BLK + NRIGHT_BLK, 128, smw>>>(fl, fr, wem, bem, wrc, brc);
    cost_kernel      <<<dim3(WL / XT, HO, NB), 256, sm2>>>(wtf, btf, out);
}

// round 8
// speedup vs baseline: 2.7464x; 1.2308x over previous
#include <cuda_runtime.h>

#define NB   2
#define CIN  16
#define CM   24
#define HIN  384
#define WIN  1280
#define HO   96
#define WL   320
#define WR   1280
#define DMAX 64

// scratch (device globals: no allocation allowed)
__device__ float g_fl[(size_t)NB*CM*HO*WL];
__device__ float g_fr[(size_t)NB*CM*HO*WR];

typedef unsigned long long ull;

__device__ __forceinline__ ull pack2(float lo, float hi) {
    ull r; asm("mov.b64 %0,{%1,%2};" : "=l"(r) : "f"(lo), "f"(hi)); return r;
}
__device__ __forceinline__ void unpack2(ull v, float& lo, float& hi) {
    asm("mov.b64 {%0,%1},%2;" : "=f"(lo), "=f"(hi) : "l"(v));
}
__device__ __forceinline__ ull fma2(ull a, ull b, ull c) {
    ull d; asm("fma.rn.f32x2 %0,%1,%2,%3;" : "=l"(d) : "l"(a), "l"(b), "l"(c)); return d;
}
__device__ __forceinline__ ull lrelu2(ull v) {
    float lo, hi; unpack2(v, lo, hi);
    lo = lo > 0.f ? lo : 0.2f * lo;
    hi = hi > 0.f ? hi : 0.2f * hi;
    return pack2(lo, hi);
}

// conv smem layout (ull units):
//   em (channel-pair, stored once):
//     s_em[(((ci*4+kh)*4)+kw)*12 + cp] = ( wem[2cp][ci][kh][kw], wem[2cp+1][ci][kh][kw] )
//   rc (duplicated for pixel-pair epilogue):
//     s_rc[co*CM + c] = ( wrc[co][c], wrc[co][c] )
//   sb_em[cp] = (bem[2cp], bem[2cp+1]);  sb_rc[co] = (brc[co], brc[co])
#define SM_EM (CIN*16*12)      // 3072 ull
#define SM_RC (CM*CM)          // 576 ull
#define SMW_ULL (SM_EM + SM_RC + 12 + CM)

#define NLEFT_BLK 240          // 2*96*160 / 128   (2 px/thread)
#define NRIGHT_BLK 960         // 2*96*640 / 128

__device__ __forceinline__ void load_weights_smem(ull* sm, const float* wem, const float* bem,
                                                  const float* wrc, const float* brc, int tid, int nthr) {
    ull* sw_em = sm;
    ull* sw_rc = sm + SM_EM;
    ull* sb_em = sw_rc + SM_RC;
    ull* sb_rc = sb_em + 12;
    for (int i = tid; i < SM_EM; i += nthr) {
        const int cp = i % 12;
        const int kw = (i / 12) & 3;
        const int r2 = i / 48;           // ci*4 + kh
        const int kh = r2 & 3, ci = r2 >> 2;
        const float w0 = wem[(((2 * cp    ) * CIN + ci) * 4 + kh) * 4 + kw];
        const float w1 = wem[(((2 * cp + 1) * CIN + ci) * 4 + kh) * 4 + kw];
        sw_em[i] = pack2(w0, w1);
    }
    for (int i = tid; i < SM_RC; i += nthr) { float w = wrc[i]; sw_rc[i] = pack2(w, w); }
    if (tid < 12) sb_em[tid] = pack2(bem[2 * tid], bem[2 * tid + 1]);
    if (tid < CM) { float v = brc[tid]; sb_rc[tid] = pack2(v, v); }
}

// acc layout: acc[px][cp] = channels (2cp, 2cp+1) for pixel px (px in 0..1)
template<bool RIGHT>
__device__ __forceinline__ void conv_body(const float* __restrict__ in, const ull* sm, int g)
{
    const ull* sw_em = sm;
    const ull* sw_rc = sm + SM_EM;
    const ull* sb_em = sw_rc + SM_RC;
    const ull* sb_rc = sb_em + 12;

    const int TPR = RIGHT ? 640 : 160;   // pixel-pairs per row
    const int t  = g % TPR;
    const int hh = (g / TPR) % HO;
    const int b  = g / (TPR * HO);

    ull acc0[12], acc1[12];
    #pragma unroll
    for (int cp = 0; cp < 12; cp++) { acc0[cp] = sb_em[cp]; acc1[cp] = sb_em[cp]; }

    const float* inb = in + (size_t)b * CIN * HIN * WIN;

    #pragma unroll 1
    for (int ci = 0; ci < CIN; ci++) {
        #pragma unroll
        for (int kh = 0; kh < 4; kh++) {
            const float* row = inb + (size_t)(ci * HIN + 4 * hh + kh) * WIN;
            ull xA[4], xB[4];   // duplicated pixel values per kw: xA = px0, xB = px1
            if (RIGHT) {
                // pixels 2t, 2t+1; input cols 2t-1 .. 2t+3 (pad: pl=1, pr=2)
                const float2 vb = *(const float2*)(row + 2 * t);
                float2 va = make_float2(0.f, 0.f);
                float2 vc = make_float2(0.f, 0.f);
                if (t > 0)   va = *(const float2*)(row + 2 * t - 2);
                if (t < 639) vc = *(const float2*)(row + 2 * t + 2);
                const float r0 = va.y, r1 = vb.x, r2 = vb.y, r3 = vc.x, r4 = vc.y;
                xA[0] = pack2(r0, r0); xA[1] = pack2(r1, r1);
                xA[2] = pack2(r2, r2); xA[3] = pack2(r3, r3);
                xB[0] = xA[1]; xB[1] = xA[2]; xB[2] = xA[3];
                xB[3] = pack2(r4, r4);
            } else {
                // pixels 2t, 2t+1; input cols 8t .. 8t+7 (stride 4, no overlap)
                const float4 v0 = *(const float4*)(row + 8 * t);
                const float4 v1 = *(const float4*)(row + 8 * t + 4);
                xA[0] = pack2(v0.x, v0.x); xA[1] = pack2(v0.y, v0.y);
                xA[2] = pack2(v0.z, v0.z); xA[3] = pack2(v0.w, v0.w);
                xB[0] = pack2(v1.x, v1.x); xB[1] = pack2(v1.y, v1.y);
                xB[2] = pack2(v1.z, v1.z); xB[3] = pack2(v1.w, v1.w);
            }
            const ull* wbase = sw_em + (ci * 4 + kh) * 48;
            #pragma unroll
            for (int kw = 0; kw < 4; kw++) {
                const ull* wrow = wbase + kw * 12;
                #pragma unroll
                for (int c2 = 0; c2 < 6; c2++) {
                    const ulonglong2 w = *(const ulonglong2*)(wrow + 2 * c2);
                    acc0[2 * c2]     = fma2(xA[kw], w.x, acc0[2 * c2]);
                    acc0[2 * c2 + 1] = fma2(xA[kw], w.y, acc0[2 * c2 + 1]);
                    acc1[2 * c2]     = fma2(xB[kw], w.x, acc1[2 * c2]);
                    acc1[2 * c2 + 1] = fma2(xB[kw], w.y, acc1[2 * c2 + 1]);
                }
            }
        }
    }

    // leaky relu, then repack in place: channel-pairs -> pixel-pairs
    // pp[2cp]   = (mid[px0][2cp],   mid[px1][2cp])
    // pp[2cp+1] = (mid[px0][2cp+1], mid[px1][2cp+1])
    ull pp[CM];
    #pragma unroll
    for (int cp = 0; cp < 12; cp++) {
        const ull a = lrelu2(acc0[cp]);
        const ull bq = lrelu2(acc1[cp]);
        float a0, a1, b0, b1;
        unpack2(a, a0, a1); unpack2(bq, b0, b1);
        pp[2 * cp]     = pack2(a0, b0);
        pp[2 * cp + 1] = pack2(a1, b1);
    }

    float* gout = RIGHT ? g_fr : g_fl;
    const int W = RIGHT ? WR : WL;

    #pragma unroll 2
    for (int co = 0; co < CM; co++) {
        ull s = sb_rc[co];
        #pragma unroll
        for (int c2 = 0; c2 < CM / 2; c2++) {
            const ulonglong2 w = *(const ulonglong2*)(sw_rc + co * CM + 2 * c2);
            s = fma2(pp[2 * c2], w.x, s);
            s = fma2(pp[2 * c2 + 1], w.y, s);
        }
        s = lrelu2(s);
        float lo, hi; unpack2(s, lo, hi);
        *(float2*)(gout + (((size_t)b * CM + co) * HO + hh) * W + 2 * t) = make_float2(lo, hi);
    }
}

__global__ void __launch_bounds__(128, 5) conv_fused_kernel(
    const float* __restrict__ inL, const float* __restrict__ inR,
    const float* __restrict__ wem, const float* __restrict__ bem,
    const float* __restrict__ wrc, const float* __restrict__ brc)
{
    extern __shared__ ull sm[];
    load_weights_smem(sm, wem, bem, wrc, brc, threadIdx.x, 128);
    __syncthreads();
    const int gb = blockIdx.x;
    if (gb < NLEFT_BLK) conv_body<false>(inL, sm, gb * 128 + threadIdx.x);
    else                conv_body<true >(inR, sm, (gb - NLEFT_BLK) * 128 + threadIdx.x);
}

// ---------------- cost volume + min/argmin + 25->13 1x1 conv + assemble ----------------
// Tiled: block = (b, h, x-tile of 64). 256 threads = 4 disparity groups x 64 x.
// smem fr window: s_fr[c][j] = fr[c][4*x0 - 66 + j], j in [0,320); float4 at smem word
// index 4k covers fr[4*x0-66+4k .. +3], so float4 idx (xl+16-dq) covers
// fr[4x-4dq-2 .. 4x-4dq+1]  ->  .w = d=4dq, .z = d=4dq+1, .y = +2, .x = +3
#define XT   64
#define FRS  324    // 320 words + pad (multiple of 4)
#define WB_PAD 340  // 13*25 + 13 = 338, padded to even word count (float2 alignment for s_red)

__global__ void __launch_bounds__(256) cost_kernel(
    const float* __restrict__ wtf, const float* __restrict__ btf, float* __restrict__ out)
{
    extern __shared__ float s[];
    float*  s_fr  = s;                             // [CM][FRS]
    float*  s_fl  = s + CM * FRS;                  // [CM][XT]
    float*  s_wtf = s_fl + CM * XT;                // 13*25
    float*  s_btf = s_wtf + 13 * 25;               // 13
    float2* s_red = (float2*)(s_fl + CM * XT + WB_PAD);  // [256], 8B-aligned (even word offset)

    const int tid = threadIdx.x;
    const int xl  = tid & 63;                 // local x
    const int dg  = tid >> 6;                 // disparity group: d in [16*dg, 16*dg+15]
    const int x0  = blockIdx.x * XT;
    const int h   = blockIdx.y, b = blockIdx.z;
    const int x   = x0 + xl;

    // ---- stage smem ----
    {
        const int G0 = 4 * x0 - 66;           // even -> float2 aligned
        #pragma unroll 1
        for (int i = tid; i < CM * 160; i += 256) {
            const int c = i / 160, p = i % 160;
            const int g = G0 + 2 * p;
            float2 v = make_float2(0.f, 0.f);
            if (g >= 0 && g < WR)
                v = *(const float2*)(g_fr + (((size_t)b * CM + c) * HO + h) * WR + g);
            s_fr[c * FRS + 2 * p]     = v.x;
            s_fr[c * FRS + 2 * p + 1] = v.y;
        }
        #pragma unroll 1
        for (int i = tid; i < CM * (XT / 4); i += 256) {
            const int c = i / (XT / 4), q = i % (XT / 4);
            *(float4*)(s_fl + c * XT + 4 * q) =
                *(const float4*)(g_fl + (((size_t)b * CM + c) * HO + h) * WL + x0 + 4 * q);
        }
        for (int i = tid; i < 13 * 25; i += 256) s_wtf[i] = wtf[i];
        if (tid < 13) s_btf[tid] = btf[tid];
    }
    __syncthreads();

    // ---- accumulate 16 disparities per thread ----
    float acc[16];
    #pragma unroll
    for (int i = 0; i < 16; i++) acc[i] = 0.f;

    if (x >= 16) {
        #pragma unroll 1
        for (int c = 0; c < CM; c++) {
            const float flc = s_fl[c * XT + xl];
            const float4* rp = (const float4*)(s_fr + c * FRS);
            #pragma unroll
            for (int q = 0; q < 4; q++) {
                const int dq = 4 * dg + q;
                const float4 v = rp[xl + 16 - dq];
                acc[4 * q + 0] += fabsf(flc - v.w);
                acc[4 * q + 1] += fabsf(flc - v.z);
                acc[4 * q + 2] += fabsf(flc - v.y);
                acc[4 * q + 3] += fabsf(flc - v.x);
            }
        }
    } else {   // only tile 0, x<16: clipped indices
        #pragma unroll 1
        for (int c = 0; c < CM; c++) {
            const float flc = s_fl[c * XT + xl];
            const float* rp = s_fr + c * FRS + 66;   // rp[i] = fr[i] (x0 == 0)
            #pragma unroll
            for (int i = 0; i < 16; i++) {
                int d = 16 * dg + i;
                int idx = 4 * x + 1 - d;
                if (idx < 0) idx = 0;
                acc[i] += fabsf(flc - rp[idx]);
            }
        }
    }

    // ---- write cost volume slice ----
    float* cv = out + (size_t)NB * 16 * HO * WL;
    #pragma unroll
    for (int i = 0; i < 16; i++) {
        const int d = 16 * dg + i;
        cv[(((size_t)b * DMAX + d) * HO + h) * WL + x] = acc[i];
    }

    // ---- per-thread min/argmin (ascending d, strict < = first occurrence) ----
    float best = acc[0]; int bi = 16 * dg;
    #pragma unroll
    for (int i = 1; i < 16; i++)
        if (acc[i] < best) { best = acc[i]; bi = 16 * dg + i; }
    s_red[tid] = make_float2(best, (float)bi);
    __syncthreads();

    // ---- final reduce + 25->13 conv + assemble (64 threads) ----
    if (tid < XT) {
        float2 r = s_red[tid];
        #pragma unroll
        for (int g2 = 1; g2 < 4; g2++) {
            const float2 o = s_red[g2 * 64 + tid];
            if (o.x < r.x) r = o;
        }

        float o13[13];
        #pragma unroll
        for (int o = 0; o < 13; o++) o13[o] = s_btf[o] + s_wtf[o * 25] * r.x;
        #pragma unroll 1
        for (int c = 0; c < CM; c++) {
            const float v = s_fl[c * XT + tid];
            #pragma unroll
            for (int o = 0; o < 13; o++) o13[o] += s_wtf[o * 25 + 1 + c] * v;
        }

        out[(((size_t)b * 16 + 0) * HO + h) * WL + x0 + tid] = r.y;
        out[(((size_t)b * 16 + 1) * HO + h) * WL + x0 + tid] = 0.f;
        out[(((size_t)b * 16 + 2) * HO + h) * WL + x0 + tid] = 0.f;
        #pragma unroll
        for (int o = 0; o < 13; o++) {
            float v = o13[o];
            v = v > 0.f ? v : 0.2f * v;
            out[(((size_t)b * 16 + 3 + o) * HO + h) * WL + x0 + tid] = v;
        }
    }
}

extern "C" void kernel_launch(void* const* d_in, const int* in_sizes, int n_in,
                              void* d_out, int out_size)
{
    const float* fl  = (const float*)d_in[0];
    const float* fr  = (const float*)d_in[1];
    // d_in[2] = max_disp (int32 scalar, fixed 64)
    const float* wem = (const float*)d_in[3];
    const float* bem = (const float*)d_in[4];
    const float* wrc = (const float*)d_in[5];
    const float* brc = (const float*)d_in[6];
    const float* wtf = (const float*)d_in[7];
    const float* btf = (const float*)d_in[8];
    float* out = (float*)d_out;

    const size_t smw = (size_t)SMW_ULL * sizeof(ull);   // ~29.5 KB
    const size_t sm2 = (size_t)(CM * FRS + CM * XT + WB_PAD) * sizeof(float)
                     + 256 * sizeof(float2);

    cudaFuncSetAttribute(conv_fused_kernel, cudaFuncAttributeMaxDynamicSharedMemorySize, (int)smw);
    cudaFuncSetAttribute(cost_kernel,       cudaFuncAttributeMaxDynamicSharedMemorySize, (int)sm2);

    conv_fused_kernel<<<NLEFT_BLK + NRIGHT_BLK, 128, smw>>>(fl, fr, wem, bem, wrc, brc);
    cost_kernel      <<<dim3(WL / XT, HO, NB), 256, sm2>>>(wtf, btf, out);
}

// round 11
// speedup vs baseline: 2.8530x; 1.0388x over previous
#include <cuda_runtime.h>

#define NB   2
#define CIN  16
#define CM   24
#define HIN  384
#define WIN  1280
#define HO   96
#define WL   320
#define WR   1280
#define DMAX 64

// scratch (device globals: no allocation allowed)
__device__ float g_fl[(size_t)NB*CM*HO*WL];
__device__ float g_fr[(size_t)NB*CM*HO*WR];

typedef unsigned long long ull;

__device__ __forceinline__ ull pack2(float lo, float hi) {
    ull r; asm("mov.b64 %0,{%1,%2};" : "=l"(r) : "f"(lo), "f"(hi)); return r;
}
__device__ __forceinline__ void unpack2(ull v, float& lo, float& hi) {
    asm("mov.b64 {%0,%1},%2;" : "=f"(lo), "=f"(hi) : "l"(v));
}
__device__ __forceinline__ ull fma2(ull a, ull b, ull c) {
    ull d; asm("fma.rn.f32x2 %0,%1,%2,%3;" : "=l"(d) : "l"(a), "l"(b), "l"(c)); return d;
}
__device__ __forceinline__ ull lrelu2(ull v) {
    float lo, hi; unpack2(v, lo, hi);
    lo = lo > 0.f ? lo : 0.2f * lo;
    hi = hi > 0.f ? hi : 0.2f * hi;
    return pack2(lo, hi);
}

// conv smem layout (ull units):
//   em (channel-pair, stored once):
//     s_em[(((ci*4+kh)*4)+kw)*12 + cp] = ( wem[2cp][ci][kh][kw], wem[2cp+1][ci][kh][kw] )
//   rc (duplicated for pixel-pair epilogue):
//     s_rc[co*CM + c] = ( wrc[co][c], wrc[co][c] )
//   sb_em[cp] = (bem[2cp], bem[2cp+1]);  sb_rc[co] = (brc[co], brc[co])
#define SM_EM (CIN*16*12)      // 3072 ull
#define SM_RC (CM*CM)          // 576 ull
#define SMW_ULL (SM_EM + SM_RC + 12 + CM)

#define NLEFT_BLK 240          // 2*96*160 / 128   (2 px/thread)
#define NRIGHT_BLK 960         // 2*96*640 / 128

__device__ __forceinline__ void load_weights_smem(ull* sm, const float* wem, const float* bem,
                                                  const float* wrc, const float* brc, int tid, int nthr) {
    ull* sw_em = sm;
    ull* sw_rc = sm + SM_EM;
    ull* sb_em = sw_rc + SM_RC;
    ull* sb_rc = sb_em + 12;
    for (int i = tid; i < SM_EM; i += nthr) {
        const int cp = i % 12;
        const int kw = (i / 12) & 3;
        const int r2 = i / 48;           // ci*4 + kh
        const int kh = r2 & 3, ci = r2 >> 2;
        const float w0 = wem[(((2 * cp    ) * CIN + ci) * 4 + kh) * 4 + kw];
        const float w1 = wem[(((2 * cp + 1) * CIN + ci) * 4 + kh) * 4 + kw];
        sw_em[i] = pack2(w0, w1);
    }
    for (int i = tid; i < SM_RC; i += nthr) { float w = wrc[i]; sw_rc[i] = pack2(w, w); }
    if (tid < 12) sb_em[tid] = pack2(bem[2 * tid], bem[2 * tid + 1]);
    if (tid < CM) { float v = brc[tid]; sb_rc[tid] = pack2(v, v); }
}

// acc layout: acc[px][cp] = channels (2cp, 2cp+1) for pixel px (px in 0..1)
template<bool RIGHT>
__device__ __forceinline__ void conv_body(const float* __restrict__ in, const ull* sm, int g)
{
    const ull* sw_em = sm;
    const ull* sw_rc = sm + SM_EM;
    const ull* sb_em = sw_rc + SM_RC;
    const ull* sb_rc = sb_em + 12;

    const int TPR = RIGHT ? 640 : 160;   // pixel-pairs per row
    const int t  = g % TPR;
    const int hh = (g / TPR) % HO;
    const int b  = g / (TPR * HO);

    ull acc0[12], acc1[12];
    #pragma unroll
    for (int cp = 0; cp < 12; cp++) { acc0[cp] = sb_em[cp]; acc1[cp] = sb_em[cp]; }

    const float* inb = in + (size_t)b * CIN * HIN * WIN;

    #pragma unroll 1
    for (int ci = 0; ci < CIN; ci++) {
        #pragma unroll
        for (int kh = 0; kh < 4; kh++) {
            const float* row = inb + (size_t)(ci * HIN + 4 * hh + kh) * WIN;
            ull xA[4], xB[4];   // duplicated pixel values per kw: xA = px0, xB = px1
            if (RIGHT) {
                // pixels 2t, 2t+1; input cols 2t-1 .. 2t+3 (pad: pl=1, pr=2)
                const float2 vb = *(const float2*)(row + 2 * t);
                float2 va = make_float2(0.f, 0.f);
                float2 vc = make_float2(0.f, 0.f);
                if (t > 0)   va = *(const float2*)(row + 2 * t - 2);
                if (t < 639) vc = *(const float2*)(row + 2 * t + 2);
                const float r0 = va.y, r1 = vb.x, r2 = vb.y, r3 = vc.x, r4 = vc.y;
                xA[0] = pack2(r0, r0); xA[1] = pack2(r1, r1);
                xA[2] = pack2(r2, r2); xA[3] = pack2(r3, r3);
                xB[0] = xA[1]; xB[1] = xA[2]; xB[2] = xA[3];
                xB[3] = pack2(r4, r4);
            } else {
                // pixels 2t, 2t+1; input cols 8t .. 8t+7 (stride 4, no overlap)
                const float4 v0 = *(const float4*)(row + 8 * t);
                const float4 v1 = *(const float4*)(row + 8 * t + 4);
                xA[0] = pack2(v0.x, v0.x); xA[1] = pack2(v0.y, v0.y);
                xA[2] = pack2(v0.z, v0.z); xA[3] = pack2(v0.w, v0.w);
                xB[0] = pack2(v1.x, v1.x); xB[1] = pack2(v1.y, v1.y);
                xB[2] = pack2(v1.z, v1.z); xB[3] = pack2(v1.w, v1.w);
            }
            const ull* wbase = sw_em + (ci * 4 + kh) * 48;
            #pragma unroll
            for (int kw = 0; kw < 4; kw++) {
                const ull* wrow = wbase + kw * 12;
                #pragma unroll
                for (int c2 = 0; c2 < 6; c2++) {
                    const ulonglong2 w = *(const ulonglong2*)(wrow + 2 * c2);
                    acc0[2 * c2]     = fma2(xA[kw], w.x, acc0[2 * c2]);
                    acc0[2 * c2 + 1] = fma2(xA[kw], w.y, acc0[2 * c2 + 1]);
                    acc1[2 * c2]     = fma2(xB[kw], w.x, acc1[2 * c2]);
                    acc1[2 * c2 + 1] = fma2(xB[kw], w.y, acc1[2 * c2 + 1]);
                }
            }
        }
    }

    // leaky relu, then repack in place: channel-pairs -> pixel-pairs
    ull pp[CM];
    #pragma unroll
    for (int cp = 0; cp < 12; cp++) {
        const ull a = lrelu2(acc0[cp]);
        const ull bq = lrelu2(acc1[cp]);
        float a0, a1, b0, b1;
        unpack2(a, a0, a1); unpack2(bq, b0, b1);
        pp[2 * cp]     = pack2(a0, b0);
        pp[2 * cp + 1] = pack2(a1, b1);
    }

    float* gout = RIGHT ? g_fr : g_fl;
    const int W = RIGHT ? WR : WL;

    #pragma unroll 2
    for (int co = 0; co < CM; co++) {
        ull s = sb_rc[co];
        #pragma unroll
        for (int c2 = 0; c2 < CM / 2; c2++) {
            const ulonglong2 w = *(const ulonglong2*)(sw_rc + co * CM + 2 * c2);
            s = fma2(pp[2 * c2], w.x, s);
            s = fma2(pp[2 * c2 + 1], w.y, s);
        }
        s = lrelu2(s);
        float lo, hi; unpack2(s, lo, hi);
        *(float2*)(gout + (((size_t)b * CM + co) * HO + hh) * W + 2 * t) = make_float2(lo, hi);
    }
}

__global__ void __launch_bounds__(128, 5) conv_fused_kernel(
    const float* __restrict__ inL, const float* __restrict__ inR,
    const float* __restrict__ wem, const float* __restrict__ bem,
    const float* __restrict__ wrc, const float* __restrict__ brc)
{
    extern __shared__ ull sm[];
    load_weights_smem(sm, wem, bem, wrc, brc, threadIdx.x, 128);
    __syncthreads();
    const int gb = blockIdx.x;
    if (gb < NLEFT_BLK) conv_body<false>(inL, sm, gb * 128 + threadIdx.x);
    else                conv_body<true >(inR, sm, (gb - NLEFT_BLK) * 128 + threadIdx.x);
}

// ---------------- cost volume + min/argmin + 25->13 1x1 conv + assemble ----------------
// Tiled: block = (b, h, x-tile of 64). 256 threads = 4 disparity groups x 64 x.
// smem fr window: s_fr[c][j] = fr[c][4*x0 - 66 + j], j in [0,320); float4 at smem word
// index 4k covers fr[4*x0-66+4k .. +3], so float4 idx (xl+16-dq) covers
// fr[4x-4dq-2 .. 4x-4dq+1]  ->  .w = d=4dq, .z = d=4dq+1, .y = +2, .x = +3
#define XT   64
#define FRS  324    // 320 words + pad (multiple of 4)
#define WB_PAD 340  // 13*25 + 13 = 338, padded to even word count (float2 alignment for s_red)

__global__ void __launch_bounds__(256) cost_kernel(
    const float* __restrict__ wtf, const float* __restrict__ btf, float* __restrict__ out)
{
    extern __shared__ float s[];
    float*  s_fr  = s;                             // [CM][FRS]
    float*  s_fl  = s + CM * FRS;                  // [CM][XT]
    float*  s_wtf = s_fl + CM * XT;                // 13*25
    float*  s_btf = s_wtf + 13 * 25;               // 13
    float2* s_red = (float2*)(s_fl + CM * XT + WB_PAD);  // [256], 8B-aligned (even word offset)

    const int tid = threadIdx.x;
    const int xl  = tid & 63;                 // local x
    const int dg  = tid >> 6;                 // disparity group: d in [16*dg, 16*dg+15]
    const int x0  = blockIdx.x * XT;
    const int h   = blockIdx.y, b = blockIdx.z;
    const int x   = x0 + xl;

    // ---- stage smem (fr loop: compile-time trip 15, unrolled 5 for MLP) ----
    {
        const int G0 = 4 * x0 - 66;           // even -> float2 aligned
        #pragma unroll 5
        for (int it = 0; it < 15; it++) {     // CM*160 / 256 == 15 exactly
            const int i = tid + it * 256;
            const int c = i / 160, p = i % 160;
            const int g = G0 + 2 * p;
            float2 v = make_float2(0.f, 0.f);
            if (g >= 0 && g < WR)
                v = *(const float2*)(g_fr + (((size_t)b * CM + c) * HO + h) * WR + g);
            s_fr[c * FRS + 2 * p]     = v.x;
            s_fr[c * FRS + 2 * p + 1] = v.y;
        }
        // fl: CM*(XT/4) = 384 -> trip 1.5; do both halves explicitly for MLP
        #pragma unroll
        for (int it = 0; it < 2; it++) {
            const int i = tid + it * 256;
            if (i < CM * (XT / 4)) {
                const int c = i / (XT / 4), q = i % (XT / 4);
                *(float4*)(s_fl + c * XT + 4 * q) =
                    *(const float4*)(g_fl + (((size_t)b * CM + c) * HO + h) * WL + x0 + 4 * q);
            }
        }
        #pragma unroll
        for (int it = 0; it < 2; it++) {
            const int i = tid + it * 256;
            if (i < 13 * 25) s_wtf[i] = wtf[i];
        }
        if (tid < 13) s_btf[tid] = btf[tid];
    }
    __syncthreads();

    // ---- accumulate 16 disparities per thread ----
    float acc[16];
    #pragma unroll
    for (int i = 0; i < 16; i++) acc[i] = 0.f;

    if (x >= 16) {
        #pragma unroll 2
        for (int c = 0; c < CM; c++) {
            const float flc = s_fl[c * XT + xl];
            const float4* rp = (const float4*)(s_fr + c * FRS);
            #pragma unroll
            for (int q = 0; q < 4; q++) {
                const int dq = 4 * dg + q;
                const float4 v = rp[xl + 16 - dq];
                acc[4 * q + 0] += fabsf(flc - v.w);
                acc[4 * q + 1] += fabsf(flc - v.z);
                acc[4 * q + 2] += fabsf(flc - v.y);
                acc[4 * q + 3] += fabsf(flc - v.x);
            }
        }
    } else {   // only tile 0, x<16: clipped indices
        #pragma unroll 2
        for (int c = 0; c < CM; c++) {
            const float flc = s_fl[c * XT + xl];
            const float* rp = s_fr + c * FRS + 66;   // rp[i] = fr[i] (x0 == 0)
            #pragma unroll
            for (int i = 0; i < 16; i++) {
                int d = 16 * dg + i;
                int idx = 4 * x + 1 - d;
                if (idx < 0) idx = 0;
                acc[i] += fabsf(flc - rp[idx]);
            }
        }
    }

    // ---- write cost volume slice ----
    float* cv = out + (size_t)NB * 16 * HO * WL;
    #pragma unroll
    for (int i = 0; i < 16; i++) {
        const int d = 16 * dg + i;
        cv[(((size_t)b * DMAX + d) * HO + h) * WL + x] = acc[i];
    }

    // ---- per-thread min/argmin (ascending d, strict < = first occurrence) ----
    float best = acc[0]; int bi = 16 * dg;
    #pragma unroll
    for (int i = 1; i < 16; i++)
        if (acc[i] < best) { best = acc[i]; bi = 16 * dg + i; }
    s_red[tid] = make_float2(best, (float)bi);
    __syncthreads();

    // ---- final reduce + 25->13 conv + assemble (64 threads) ----
    if (tid < XT) {
        float2 r = s_red[tid];
        #pragma unroll
        for (int g2 = 1; g2 < 4; g2++) {
            const float2 o = s_red[g2 * 64 + tid];
            if (o.x < r.x) r = o;
        }

        float o13[13];
        #pragma unroll
        for (int o = 0; o < 13; o++) o13[o] = s_btf[o] + s_wtf[o * 25] * r.x;
        #pragma unroll 2
        for (int c = 0; c < CM; c++) {
            const float v = s_fl[c * XT + tid];
            #pragma unroll
            for (int o = 0; o < 13; o++) o13[o] += s_wtf[o * 25 + 1 + c] * v;
        }

        out[(((size_t)b * 16 + 0) * HO + h) * WL + x0 + tid] = r.y;
        out[(((size_t)b * 16 + 1) * HO + h) * WL + x0 + tid] = 0.f;
        out[(((size_t)b * 16 + 2) * HO + h) * WL + x0 + tid] = 0.f;
        #pragma unroll
        for (int o = 0; o < 13; o++) {
            float v = o13[o];
            v = v > 0.f ? v : 0.2f * v;
            out[(((size_t)b * 16 + 3 + o) * HO + h) * WL + x0 + tid] = v;
        }
    }
}

extern "C" void kernel_launch(void* const* d_in, const int* in_sizes, int n_in,
                              void* d_out, int out_size)
{
    const float* fl  = (const float*)d_in[0];
    const float* fr  = (const float*)d_in[1];
    // d_in[2] = max_disp (int32 scalar, fixed 64)
    const float* wem = (const float*)d_in[3];
    const float* bem = (const float*)d_in[4];
    const float* wrc = (const float*)d_in[5];
    const float* brc = (const float*)d_in[6];
    const float* wtf = (const float*)d_in[7];
    const float* btf = (const float*)d_in[8];
    float* out = (float*)d_out;

    const size_t smw = (size_t)SMW_ULL * sizeof(ull);   // ~29.5 KB
    const size_t sm2 = (size_t)(CM * FRS + CM * XT + WB_PAD) * sizeof(float)
                     + 256 * sizeof(float2);

    cudaFuncSetAttribute(conv_fused_kernel, cudaFuncAttributeMaxDynamicSharedMemorySize, (int)smw);
    cudaFuncSetAttribute(cost_kernel,       cudaFuncAttributeMaxDynamicSharedMemorySize, (int)sm2);

    conv_fused_kernel<<<NLEFT_BLK + NRIGHT_BLK, 128, smw>>>(fl, fr, wem, bem, wrc, brc);
    cost_kernel      <<<dim3(WL / XT, HO, NB), 256, sm2>>>(wtf, btf, out);
}